// round 11
// baseline (speedup 1.0000x reference)
#include <cuda_runtime.h>
#include <cuda_fp16.h>
#include <stdint.h>

#define BB 4
#define SS 1024
#define HH 32
#define KVHH 8
#define DD 128
#define QTILE 128
#define KTILE 64
#define WIN 512
#define NT 256
#define NSLOT 4

#define KV_ELEMS (BB * SS * KVHH * DD)   // 4194304

// fp16 K/V scratch (pre-converted by convert_kv kernel)
__device__ __half KH[KV_ELEMS];
__device__ __half VH[KV_ELEMS];

// smem: Q 32KB + ring 4 x (K 16KB + V 16KB) = 128KB + barriers
#define QBYTES (128 * 256)
#define KBYTES (64 * 256)
#define BAR_OFF (QBYTES + NSLOT * 2 * KBYTES)   // 163840
#define SMEM_BYTES (BAR_OFF + NSLOT * 16)

__device__ __forceinline__ uint32_t swadr(uint32_t base, int row, int chunk) {
    return base + row * 256 + ((chunk ^ (row & 7)) << 4);
}
__device__ __forceinline__ float tanh_fast(float x) {
    float y; asm("tanh.approx.f32 %0, %1;" : "=f"(y) : "f"(x)); return y;
}
__device__ __forceinline__ float ex2(float x) {
    float y; asm("ex2.approx.f32 %0, %1;" : "=f"(y) : "f"(x)); return y;
}
__device__ __forceinline__ uint32_t ex2h2(uint32_t a) {
    uint32_t d; asm("ex2.approx.f16x2 %0, %1;" : "=r"(d) : "r"(a)); return d;
}
__device__ __forceinline__ uint32_t pk(float lo, float hi) {
    __half2 h = __floats2half2_rn(lo, hi);
    return *(uint32_t*)&h;
}
__device__ __forceinline__ void ldsm4(uint32_t& r0, uint32_t& r1, uint32_t& r2, uint32_t& r3, uint32_t a) {
    asm volatile("ldmatrix.sync.aligned.m8n8.x4.shared.b16 {%0,%1,%2,%3},[%4];"
                 : "=r"(r0), "=r"(r1), "=r"(r2), "=r"(r3) : "r"(a));
}
__device__ __forceinline__ void ldsm4t(uint32_t& r0, uint32_t& r1, uint32_t& r2, uint32_t& r3, uint32_t a) {
    asm volatile("ldmatrix.sync.aligned.m8n8.x4.trans.shared.b16 {%0,%1,%2,%3},[%4];"
                 : "=r"(r0), "=r"(r1), "=r"(r2), "=r"(r3) : "r"(a));
}
__device__ __forceinline__ void mma16(float* d, uint32_t a0, uint32_t a1, uint32_t a2, uint32_t a3,
                                      uint32_t b0, uint32_t b1) {
    asm volatile(
        "mma.sync.aligned.m16n8k16.row.col.f32.f16.f16.f32 "
        "{%0,%1,%2,%3}, {%4,%5,%6,%7}, {%8,%9}, {%0,%1,%2,%3};"
        : "+f"(d[0]), "+f"(d[1]), "+f"(d[2]), "+f"(d[3])
        : "r"(a0), "r"(a1), "r"(a2), "r"(a3), "r"(b0), "r"(b1));
}
__device__ __forceinline__ void cpa16(uint32_t dst, const __half* src) {
    asm volatile("cp.async.cg.shared.global [%0], [%1], 16;" :: "r"(dst), "l"(src));
}
__device__ __forceinline__ void mbar_init(uint32_t a, uint32_t cnt) {
    asm volatile("mbarrier.init.shared.b64 [%0], %1;" :: "r"(a), "r"(cnt) : "memory");
}
__device__ __forceinline__ void mbar_arrive(uint32_t a) {
    asm volatile("mbarrier.arrive.release.cta.shared::cta.b64 _, [%0];" :: "r"(a) : "memory");
}
__device__ __forceinline__ void cpa_arrive(uint32_t a) {
    asm volatile("cp.async.mbarrier.arrive.noinc.shared::cta.b64 [%0];" :: "r"(a) : "memory");
}
__device__ __forceinline__ void mbar_wait(uint32_t a, uint32_t parity) {
    asm volatile(
        "{\n\t.reg .pred P1;\n\t"
        "WAIT_LOOP_%=:\n\t"
        "mbarrier.try_wait.parity.acquire.cta.shared::cta.b64 P1, [%0], %1, 0x989680;\n\t"
        "@P1 bra.uni WAIT_DONE_%=;\n\t"
        "bra.uni WAIT_LOOP_%=;\n\t"
        "WAIT_DONE_%=:\n\t}"
        :: "r"(a), "r"(parity) : "memory");
}

// ---- pre-pass: fp32 -> fp16 (round-to-nearest) for K and V ----
__global__ __launch_bounds__(256, 8)
void convert_kv(const float* __restrict__ k, const float* __restrict__ v) {
    const int i = (blockIdx.x * 256 + threadIdx.x) * 8;
    float4 a = *(const float4*)&k[i];
    float4 b = *(const float4*)&k[i + 4];
    uint4 u;
    u.x = pk(a.x, a.y); u.y = pk(a.z, a.w); u.z = pk(b.x, b.y); u.w = pk(b.z, b.w);
    *(uint4*)&KH[i] = u;
    a = *(const float4*)&v[i];
    b = *(const float4*)&v[i + 4];
    u.x = pk(a.x, a.y); u.y = pk(a.z, a.w); u.z = pk(b.x, b.y); u.w = pk(b.z, b.w);
    *(uint4*)&VH[i] = u;
}

__global__ __launch_bounds__(NT, 1)
void attn_kernel(const float* __restrict__ q, float* __restrict__ out)
{
    extern __shared__ char smraw[];
    uint32_t smb;
    asm("{ .reg .u64 t; cvta.to.shared.u64 t, %1; cvt.u32.u64 %0, t; }" : "=r"(smb) : "l"(smraw));
    const uint32_t Qb = smb, Rb = smb + QBYTES, Bar = smb + BAR_OFF;
    // full[s] = Bar + 16s ; empty[s] = Bar + 16s + 8

    const int qt = blockIdx.x, h = blockIdx.y, b = blockIdx.z;
    const int kvh = h >> 2;
    const int q0  = qt * QTILE;
    const int tid = threadIdx.x, lane = tid & 31, w = tid >> 5;
    const int g = lane >> 2, tg = lane & 3;

    const int lr = tid >> 4;   // 0..15
    const int lc = tid & 15;   // chunk 0..15

    const int rowA  = 16 * w + (lane & 7) + 8 * ((lane >> 3) & 1);
    const int cA    = lane >> 4;
    const int rowB  = (lane & 7) + 8 * (lane >> 4);
    const int cB    = (lane >> 3) & 1;
    const int rowV_ = (lane & 7) + 8 * ((lane >> 3) & 1);
    const int cV    = lane >> 4;

    const int lo = (q0 - WIN + 1 > 0) ? ((q0 - WIN + 1) >> 6) : 0;
    const int hi = (q0 + QTILE - 1) >> 6;

    const float qscale = 0.08838834764831843f * 0.02f;   // (1/sqrt(128)) / 50
    const float CC = 72.13475204444817f;                 // 50 * log2(e)
    const uint32_t ONE2 = 0x3C003C00u;                   // h2(1,1)

    // ---- init mbarriers before any cp.async targets them ----
    if (tid == 0) {
        #pragma unroll
        for (int s = 0; s < NSLOT; s++) {
            mbar_init(Bar + 16 * s,     NT);   // full: 256 async-group arrivals
            mbar_init(Bar + 16 * s + 8, NT);   // empty: 256 thread arrivals
        }
    }
    __syncthreads();

    // issue this thread's cp.async portion of tile t into slot (t-lo)&3
    auto issue_tile = [&](int t) {
        const int slot = (t - lo) & (NSLOT - 1);
        const int j0 = t * KTILE;
        const uint32_t Kd = Rb + slot * 2 * KBYTES;
        const uint32_t Vd = Kd + KBYTES;
        const __half* kp = KH + ((size_t)((b * SS + j0 + lr) * KVHH + kvh)) * DD + 8 * lc;
        const __half* vp = VH + ((size_t)((b * SS + j0 + lr) * KVHH + kvh)) * DD + 8 * lc;
        #pragma unroll
        for (int it = 0; it < 4; it++) {
            const int r = lr + 16 * it;
            cpa16(swadr(Kd, r, lc), kp + (size_t)16 * it * KVHH * DD);
            cpa16(swadr(Vd, r, lc), vp + (size_t)16 * it * KVHH * DD);
        }
        cpa_arrive(Bar + 16 * slot);
    };

    // ---- prologue: issue up to 3 tiles ----
    issue_tile(lo);
    if (lo + 1 <= hi) issue_tile(lo + 1);
    if (lo + 2 <= hi) issue_tile(lo + 2);

    // ---- Q: LDG -> scale -> fp16 -> swizzled STS ----
    #pragma unroll
    for (int it = 0; it < 8; it++) {
        const int r = lr + 16 * it;
        const float* qp = q + ((size_t)((b * SS + q0 + r) * HH + h)) * DD + 8 * lc;
        float4 f0 = *(const float4*)qp;
        float4 f1 = *(const float4*)(qp + 4);
        uint4 u;
        u.x = pk(f0.x * qscale, f0.y * qscale);
        u.y = pk(f0.z * qscale, f0.w * qscale);
        u.z = pk(f1.x * qscale, f1.y * qscale);
        u.w = pk(f1.z * qscale, f1.w * qscale);
        asm volatile("st.shared.v4.b32 [%0], {%1,%2,%3,%4};"
                     :: "r"(swadr(Qb, r, lc)), "r"(u.x), "r"(u.y), "r"(u.z), "r"(u.w));
    }
    __syncthreads();

    // ---- Q fragments -> registers (held for whole kernel) ----
    uint32_t qf[8][4];
    #pragma unroll
    for (int i = 0; i < 8; i++)
        ldsm4(qf[i][0], qf[i][1], qf[i][2], qf[i][3], swadr(Qb, rowA, 2 * i + cA));

    float o[16][4];
    #pragma unroll
    for (int t = 0; t < 16; t++) { o[t][0] = 0.f; o[t][1] = 0.f; o[t][2] = 0.f; o[t][3] = 0.f; }
    float accl[4] = {0.f, 0.f, 0.f, 0.f};
    // softmax kept in "tanh units": sigma = tanh(.) in [-1,1]; score = 50*sigma.
    // m init -1.02 is a strict lower bound of any real sigma -> m finite always.
    float m0 = -1.02f, m1 = -1.02f;

    const int rlo = q0 + 16 * w, rhi = rlo + 15;
    const int ig0 = rlo + g, ig1 = ig0 + 8;

    float sA[8][4], sB[8][4];

    // QK of tile T (slot ready) into S
    #define QK_TILE(T, S) do {                                                     \
        const uint32_t Kc_ = Rb + (((T) - lo) & (NSLOT - 1)) * 2 * KBYTES;         \
        _Pragma("unroll")                                                          \
        for (int t_ = 0; t_ < 8; t_++) {                                           \
            S[t_][0] = 0.f; S[t_][1] = 0.f; S[t_][2] = 0.f; S[t_][3] = 0.f; }      \
        _Pragma("unroll")                                                          \
        for (int i_ = 0; i_ < 8; i_++) {                                           \
            _Pragma("unroll")                                                      \
            for (int p_ = 0; p_ < 4; p_++) {                                       \
                uint32_t b0_, b1_, b2_, b3_;                                       \
                ldsm4(b0_, b1_, b2_, b3_, swadr(Kc_, rowB + 16 * p_, 2 * i_ + cB));\
                mma16(S[2 * p_],     qf[i_][0], qf[i_][1], qf[i_][2], qf[i_][3], b0_, b1_); \
                mma16(S[2 * p_ + 1], qf[i_][0], qf[i_][1], qf[i_][2], qf[i_][3], b2_, b3_); \
            } }                                                                    \
    } while (0)

    // full body for tile KT: issue KT+3, prefetch-QK KT+1 into SNEXT, softmax+PV on SCUR
    #define TILE_BODY(KT, SCUR, SNEXT) do {                                        \
        const int ti_ = (KT) - lo;                                                 \
        if ((KT) + 3 <= hi) {                                                      \
            const int xi_ = ti_ + 3, sl3_ = xi_ & (NSLOT - 1);                     \
            if (xi_ >= NSLOT) mbar_wait(Bar + 16 * sl3_ + 8, ((xi_ >> 2) - 1) & 1);\
            issue_tile((KT) + 3);                                                  \
        }                                                                          \
        if ((KT) < hi) {                                                           \
            const int tn_ = ti_ + 1;                                               \
            mbar_wait(Bar + 16 * (tn_ & (NSLOT - 1)), (tn_ >> 2) & 1);             \
            QK_TILE((KT) + 1, SNEXT);                                              \
        }                                                                          \
        const int j0_   = (KT) * KTILE;                                            \
        const int slot_ = ti_ & (NSLOT - 1);                                       \
        const bool active_ = (j0_ <= rhi) && (j0_ + KTILE - 1 >= rlo - WIN + 1);   \
        if (active_) {                                                             \
            const uint32_t Vc_ = Rb + slot_ * 2 * KBYTES + KBYTES;                 \
            const bool masked_ = (j0_ + KTILE - 1 > rlo) || (rhi - j0_ >= WIN);    \
            float rmax0 = -1e30f, rmax1 = -1e30f;                                  \
            if (masked_) {                                                         \
                _Pragma("unroll")                                                  \
                for (int t_ = 0; t_ < 8; t_++) {                                   \
                    const int jg_ = j0_ + 8 * t_ + 2 * tg;                         \
                    float v0 = tanh_fast(SCUR[t_][0]);                             \
                    float v1 = tanh_fast(SCUR[t_][1]);                             \
                    float v2 = tanh_fast(SCUR[t_][2]);                             \
                    float v3 = tanh_fast(SCUR[t_][3]);                             \
                    bool ok0 = (jg_     <= ig0) && (ig0 - jg_     < WIN);          \
                    bool ok1 = (jg_ + 1 <= ig0) && (ig0 - jg_ - 1 < WIN);          \
                    bool ok2 = (jg_     <= ig1) && (ig1 - jg_     < WIN);          \
                    bool ok3 = (jg_ + 1 <= ig1) && (ig1 - jg_ - 1 < WIN);          \
                    SCUR[t_][0] = ok0 ? v0 : -1e30f;                               \
                    SCUR[t_][1] = ok1 ? v1 : -1e30f;                               \
                    SCUR[t_][2] = ok2 ? v2 : -1e30f;                               \
                    SCUR[t_][3] = ok3 ? v3 : -1e30f;                               \
                    rmax0 = fmaxf(rmax0, fmaxf(SCUR[t_][0], SCUR[t_][1]));         \
                    rmax1 = fmaxf(rmax1, fmaxf(SCUR[t_][2], SCUR[t_][3]));         \
                }                                                                  \
            } else {                                                               \
                _Pragma("unroll")                                                  \
                for (int t_ = 0; t_ < 8; t_++) {                                   \
                    SCUR[t_][0] = tanh_fast(SCUR[t_][0]);                          \
                    SCUR[t_][1] = tanh_fast(SCUR[t_][1]);                          \
                    SCUR[t_][2] = tanh_fast(SCUR[t_][2]);                          \
                    SCUR[t_][3] = tanh_fast(SCUR[t_][3]);                          \
                    rmax0 = fmaxf(rmax0, fmaxf(SCUR[t_][0], SCUR[t_][1]));         \
                    rmax1 = fmaxf(rmax1, fmaxf(SCUR[t_][2], SCUR[t_][3]));         \
                }                                                                  \
            }                                                                      \
            rmax0 = fmaxf(rmax0, __shfl_xor_sync(0xffffffffu, rmax0, 1));          \
            rmax0 = fmaxf(rmax0, __shfl_xor_sync(0xffffffffu, rmax0, 2));          \
            rmax1 = fmaxf(rmax1, __shfl_xor_sync(0xffffffffu, rmax1, 1));          \
            rmax1 = fmaxf(rmax1, __shfl_xor_sync(0xffffffffu, rmax1, 2));          \
            const float m0n = fmaxf(m0, rmax0);                                    \
            const float m1n = fmaxf(m1, rmax1);                                    \
            const float al0 = ex2((m0 - m0n) * CC);                                \
            const float al1 = ex2((m1 - m1n) * CC);                                \
            m0 = m0n; m1 = m1n;                                                    \
            const float mC0 = m0n * CC, mC1 = m1n * CC;                            \
            _Pragma("unroll")                                                      \
            for (int t_ = 0; t_ < 16; t_++) {                                      \
                o[t_][0] *= al0; o[t_][1] *= al0; o[t_][2] *= al1; o[t_][3] *= al1; } \
            accl[0] *= al0; accl[1] *= al0; accl[2] *= al1; accl[3] *= al1;        \
            _Pragma("unroll")                                                      \
            for (int u_ = 0; u_ < 4; u_++) {                                       \
                const uint32_t a0 = ex2h2(pk(SCUR[2*u_][0]   * CC - mC0, SCUR[2*u_][1]   * CC - mC0)); \
                const uint32_t a1 = ex2h2(pk(SCUR[2*u_][2]   * CC - mC1, SCUR[2*u_][3]   * CC - mC1)); \
                const uint32_t a2 = ex2h2(pk(SCUR[2*u_+1][0] * CC - mC0, SCUR[2*u_+1][1] * CC - mC0)); \
                const uint32_t a3 = ex2h2(pk(SCUR[2*u_+1][2] * CC - mC1, SCUR[2*u_+1][3] * CC - mC1)); \
                mma16(accl, a0, a1, a2, a3, ONE2, ONE2);                           \
                _Pragma("unroll")                                                  \
                for (int p_ = 0; p_ < 8; p_++) {                                   \
                    uint32_t b0_, b1_, b2_, b3_;                                   \
                    ldsm4t(b0_, b1_, b2_, b3_, swadr(Vc_, 16 * u_ + rowV_, 2 * p_ + cV)); \
                    mma16(o[2 * p_],     a0, a1, a2, a3, b0_, b1_);                \
                    mma16(o[2 * p_ + 1], a0, a1, a2, a3, b2_, b3_);                \
                } }                                                                \
        }                                                                          \
        mbar_arrive(Bar + 16 * slot_ + 8);                                         \
    } while (0)

    // ---- prologue: QK of first tile ----
    mbar_wait(Bar + 0, 0);         // full[slot 0], phase 0
    QK_TILE(lo, sA);

    // ---- main loop, ping-pong sA/sB ----
    for (int kt = lo; kt <= hi; kt += 2) {
        TILE_BODY(kt, sA, sB);
        if (kt + 1 <= hi) TILE_BODY(kt + 1, sB, sA);
    }

    // ---- write output (accl[0] = l for row ig0, accl[2] = l for row ig1) ----
    const float inv0 = 1.f / accl[0];
    const float inv1 = 1.f / accl[2];
    const size_t base0 = ((size_t)((b * SS + ig0) * HH + h)) * DD;
    const size_t base1 = ((size_t)((b * SS + ig1) * HH + h)) * DD;
    #pragma unroll
    for (int t = 0; t < 16; t++) {
        const int col = 8 * t + 2 * tg;
        *(float2*)&out[base0 + col] = make_float2(o[t][0] * inv0, o[t][1] * inv0);
        *(float2*)&out[base1 + col] = make_float2(o[t][2] * inv1, o[t][3] * inv1);
    }
}

extern "C" void kernel_launch(void* const* d_in, const int* in_sizes, int n_in,
                              void* d_out, int out_size)
{
    const float* q = (const float*)d_in[0];   // query  [4096,32,128]
    const float* k = (const float*)d_in[1];   // key    [4096, 8,128]
    const float* v = (const float*)d_in[2];   // value  [4096, 8,128]
    // d_in[3..5] (caches + block table) do not affect the output: the cache
    // write-then-gather of the same permutation blocks returns key/value unchanged.
    float* out = (float*)d_out;

    convert_kv<<<KV_ELEMS / (256 * 8), 256>>>(k, v);

    cudaFuncSetAttribute(attn_kernel,
                         cudaFuncAttributeMaxDynamicSharedMemorySize,
                         SMEM_BYTES);
    dim3 grid(SS / QTILE, HH, BB);   // 8 x 32 x 4 = 1024 blocks
    attn_kernel<<<grid, NT, SMEM_BYTES>>>(q, out);
}